// round 10
// baseline (speedup 1.0000x reference)
#include <cuda_runtime.h>
#include <math.h>

// MHFSpectralConv2D via pruned-DFT factorization, round 10 (= round-8 source;
// never ran due to container failure; fully re-audited — fold algebra,
// LDS.128 alignment (pp always even), barrier placement, smem extents all
// verified. Resubmitted byte-identical).
// k12: fused forward (2-rows/thread folded w-DFT, TK via __ldg, x via __ldcs,
//      twiddle-recurrence h-DFT) -> XfT[f][img]
// k2b: weight transpose   k3: per-freq complex mix
// k45: fused inverse (recurrence h-DFT -> Gp smem -> LDS.128 row-quad folded
//      f32x2 w-synthesis).

namespace {
constexpr int IMG = 512;                      // B*C = 8*64
constexpr int MX = 32, MY = 17, F = MX * MY;  // 544 live freqs
constexpr int XSS = 260;                      // k12 x-stage row stride
}

// ---- persistent device scratch / tables ----
__device__ float  g_TK1[129 * 36];   // [w][36]: cos ky 0..16 | 0 | -sin | 0
__device__ float2 g_E1[32];          // e(+2pi kx/256)
__device__ float2 g_Eseed[256];      // [ch*32+kx] = e(+2pi kx*32*ch/256)
__device__ float2 g_Estep[256];      // [h] = e(+2pi h/256)
__device__ float2 g_PC5[17 * 128];   // K5 cos coef, duplicated lanes
__device__ float2 g_PS5[17 * 128];   // K5 sin coef, duplicated lanes
__device__ float2 g_XfT[(size_t)F * IMG];     // [f][img]
__device__ float2 g_WT[(size_t)F * 4096];     // [f][i*64+co]
__device__ float2 g_YfT[(size_t)F * IMG];     // [f][img]

// ---- f32x2 helpers ----
typedef unsigned long long u64;
__device__ __forceinline__ u64 ffma2(u64 a, u64 b, u64 c) {
    u64 d;
    asm("fma.rn.f32x2 %0, %1, %2, %3;" : "=l"(d) : "l"(a), "l"(b), "l"(c));
    return d;
}
__device__ __forceinline__ float2 upk(u64 v) {
    float2 r;
    asm("mov.b64 {%0,%1}, %2;" : "=f"(r.x), "=f"(r.y) : "l"(v));
    return r;
}
__device__ __forceinline__ u64 pk(float a, float b) {
    u64 v;
    asm("mov.b64 %0, {%1,%2};" : "=l"(v) : "f"(a), "f"(b));
    return v;
}

// ---------------------------------------------------------------------------
// K0a/K0b: trig tables (exact integer mod-256 reduction).
// ---------------------------------------------------------------------------
__global__ void k0a_tables() {
    int tid = blockIdx.x * blockDim.x + threadIdx.x;
    int nt  = blockDim.x * gridDim.x;
    for (int idx = tid; idx < 129 * 36; idx += nt) {
        int w = idx / 36, c = idx % 36;
        float v = 0.f;
        if (c < 17) {
            int m = (c * w) & 255; float s, co;
            sincospif((float)m * (1.f / 128.f), &s, &co);
            v = co;
        } else if (c >= 18 && c < 35) {
            int ky = c - 18;
            int m = (ky * w) & 255; float s, co;
            sincospif((float)m * (1.f / 128.f), &s, &co);
            v = -s;
        }
        g_TK1[idx] = v;
    }
    for (int idx = tid; idx < 256; idx += nt) {
        float s, co;
        if (idx < 32) {
            int m = idx & 255;
            sincospif((float)m * (1.f / 128.f), &s, &co);
            g_E1[idx] = make_float2(co, s);
        }
        {
            int ch = idx >> 5, kx = idx & 31;
            int m = (32 * ch * kx) & 255;
            sincospif((float)m * (1.f / 128.f), &s, &co);
            g_Eseed[idx] = make_float2(co, s);
        }
        {
            int m = idx & 255;
            sincospif((float)m * (1.f / 128.f), &s, &co);
            g_Estep[idx] = make_float2(co, s);
        }
    }
}
__global__ void k0b_tables() {
    int tid = blockIdx.x * blockDim.x + threadIdx.x;
    int nt  = blockDim.x * gridDim.x;
    for (int idx = tid; idx < 17 * 128; idx += nt) {
        int k = idx >> 7, w = idx & 127;
        int m = (k * w) & 255; float s, co;
        sincospif((float)m * (1.f / 128.f), &s, &co);
        float ce = (k == 0) ? (1.f / 256.f) : co * (2.f / 256.f);
        float cs = -s * (2.f / 256.f);
        g_PC5[idx] = make_float2(ce, ce);
        g_PS5[idx] = make_float2(cs, cs);
    }
}

// ---------------------------------------------------------------------------
// K2b: weight transpose -> WT[f][i*64 + co] (co = hd*16 + o).
// ---------------------------------------------------------------------------
__global__ void __launch_bounds__(256) k2b_wt(const float* __restrict__ wr,
                                             const float* __restrict__ wi) {
    extern __shared__ float smw[];
    float* smr = smw;            // 16*545
    float* smi = smw + 16 * 545; // 16*545

    int hd = blockIdx.x >> 6, i = blockIdx.x & 63;
    size_t base = (size_t)((hd * 64 + i) * 16) * F;   // 16 rows x 544

    const float4* wr4 = reinterpret_cast<const float4*>(wr + base);
    const float4* wi4 = reinterpret_cast<const float4*>(wi + base);
    for (int idx = threadIdx.x; idx < 2176; idx += 256) {
        int o = (idx * 4) / 544, fb = (idx * 4) % 544;
        float4 a = wr4[idx];
        float4 b = wi4[idx];
        float* dr = smr + o * 545 + fb;
        float* di = smi + o * 545 + fb;
        dr[0] = a.x; dr[1] = a.y; dr[2] = a.z; dr[3] = a.w;
        di[0] = b.x; di[1] = b.y; di[2] = b.z; di[3] = b.w;
    }
    __syncthreads();

    int cobase = i * 64 + hd * 16;
    for (int idx = threadIdx.x; idx < 8704; idx += 256) {
        int f = idx >> 4, o = idx & 15;
        g_WT[(size_t)f * 4096 + cobase + o] =
            make_float2(smr[o * 545 + f], smi[o * 545 + f]);
    }
}

// ---------------------------------------------------------------------------
// K12: fused forward transform, block per image (512 blocks, 256 threads).
// Phase 1 (x4 chunks of 64 rows): folded w-DFT, 2 rows/thread.
// Thread (rp = t>>3, p = t&7) handles rows 2rp,2rp+1 and w = 8j+p+1, j=0..15.
// Xs stride 260 -> conflict-free fold reads. TK via __ldg (L1-resident;
// x staged with __ldcs); each table u64 feeds BOTH rows.
// Reduce 8 partials: 2 bfly rounds -> 2 partials -> red (aliases Xs, barrier-
// separated) -> Aw[row][36] in smem.
// Phase 2: h-DFT from smem Aw (broadcast u64) + twiddle recurrence
// E(h+1) = E(h)*E1[kx] seeded from g_Eseed.
// ---------------------------------------------------------------------------
__global__ void __launch_bounds__(256) k12_fwd(const float* __restrict__ x) {
    extern __shared__ __align__(16) float sm[];
    float* Xs = sm;              // 64*260 = 16640 (red / red2 alias here)
    float* Aw = sm + 16640;      // 256*36 = 9216

    int t = threadIdx.x;
    int img = blockIdx.x;
    int p = t & 7, rp = t >> 3;          // rp 0..31
    float* red = Xs;                     // 64 rows * 2 parts * 37 = 4736
    const u64* TKg = reinterpret_cast<const u64*>(g_TK1);

    for (int chunk = 0; chunk < 4; chunk++) {
        __syncthreads();   // prior red consumers done; Xs free
        const float4* xg = reinterpret_cast<const float4*>(
            x + (size_t)img * 65536 + chunk * 16384);
#pragma unroll
        for (int k = 0; k < 16; k++) {
            int fidx = k * 256 + t;
            int row = fidx >> 6, c4 = fidx & 63;
            float4 v = __ldcs(xg + fidx);
            *reinterpret_cast<float4*>(Xs + row * XSS + c4 * 4) = v;
        }
        __syncthreads();

        const float* xr0 = Xs + (2 * rp) * XSS;
        const float* xr1 = xr0 + XSS;

        u64 a0[18], a1[18];
#pragma unroll
        for (int q = 0; q < 18; q++) { a0[q] = 0; a1[q] = 0; }

#pragma unroll 2
        for (int j = 0; j < 16; j++) {
            int w = 8 * j + p + 1;
            float f0 = xr0[w], m0 = xr0[256 - w];
            float f1 = xr1[w], m1 = xr1[256 - w];
            u64 uu0 = pk(f0 + m0, f0 + m0), vv0 = pk(f0 - m0, f0 - m0);
            u64 uu1 = pk(f1 + m1, f1 + m1), vv1 = pk(f1 - m1, f1 - m1);
            const u64* tu = TKg + w * 18;
#pragma unroll
            for (int q = 0; q < 9; q++) {
                u64 tv = __ldg(tu + q);
                a0[q] = ffma2(tv, uu0, a0[q]);
                a1[q] = ffma2(tv, uu1, a1[q]);
            }
#pragma unroll
            for (int q = 9; q < 18; q++) {
                u64 tv = __ldg(tu + q);
                a0[q] = ffma2(tv, vv0, a0[q]);
                a1[q] = ffma2(tv, vv1, a1[q]);
            }
        }
        if (p == 0) {
            float x00 = xr0[0], x80 = xr0[128];
            float ea0 = x00 - x80, eb0 = x00 + x80;
            u64 e0 = pk(ea0, eb0), one2 = pk(1.f, 1.f);
            float x01 = xr1[0], x81 = xr1[128];
            float ea1 = x01 - x81, eb1 = x01 + x81;
            u64 e1 = pk(ea1, eb1);
#pragma unroll
            for (int q = 0; q < 8; q++) {
                a0[q] = ffma2(one2, e0, a0[q]);
                a1[q] = ffma2(one2, e1, a1[q]);
            }
            a0[8] = ffma2(one2, pk(ea0, 0.f), a0[8]);
            a1[8] = ffma2(one2, pk(ea1, 0.f), a1[8]);
        }

        // All warps done reading Xs before red (aliased) is written.
        __syncthreads();

        bool wrt = (p == 0) | (p == 4);
        int part = p >> 2;
        int rb0 = ((2 * rp) * 2 + part) * 37;
        int rb1 = ((2 * rp + 1) * 2 + part) * 37;
#pragma unroll
        for (int q = 0; q < 18; q++) {
            float2 v = upk(a0[q]);
            v.x += __shfl_xor_sync(0xffffffffu, v.x, 1);
            v.y += __shfl_xor_sync(0xffffffffu, v.y, 1);
            v.x += __shfl_xor_sync(0xffffffffu, v.x, 2);
            v.y += __shfl_xor_sync(0xffffffffu, v.y, 2);
            if (wrt) { red[rb0 + 2 * q] = v.x; red[rb0 + 2 * q + 1] = v.y; }
            float2 u = upk(a1[q]);
            u.x += __shfl_xor_sync(0xffffffffu, u.x, 1);
            u.y += __shfl_xor_sync(0xffffffffu, u.y, 1);
            u.x += __shfl_xor_sync(0xffffffffu, u.x, 2);
            u.y += __shfl_xor_sync(0xffffffffu, u.y, 2);
            if (wrt) { red[rb1 + 2 * q] = u.x; red[rb1 + 2 * q + 1] = u.y; }
        }
        __syncthreads();

        for (int idx = t; idx < 64 * 36; idx += 256) {
            int row = idx / 36, c = idx % 36;
            Aw[(chunk * 64 + row) * 36 + c] =
                red[(row * 2) * 37 + c] + red[(row * 2 + 1) * 37 + c];
        }
    }
    __syncthreads();

    // ---- Phase 2: h-DFT with twiddle recurrence ----
    int kx = t & 31, ch = t >> 5;
    float2 E = g_Eseed[ch * 32 + kx];
    float2 S = g_E1[kx];
    u64 accRe[9], accIm[9];
#pragma unroll
    for (int q = 0; q < 9; q++) { accRe[q] = 0; accIm[q] = 0; }

#pragma unroll 4
    for (int hh = 0; hh < 32; hh++) {
        int h = ch * 32 + hh;
        u64 Ex2  = pk(E.x, E.x);
        u64 Ey2  = pk(E.y, E.y);
        u64 Eyn2 = pk(-E.y, -E.y);
        const u64* c2 = reinterpret_cast<const u64*>(Aw + h * 36);
#pragma unroll
        for (int q = 0; q < 9; q++) {
            u64 cr = c2[q], ci = c2[9 + q];
            accRe[q] = ffma2(cr, Ex2, accRe[q]);
            accRe[q] = ffma2(ci, Ey2, accRe[q]);
            accIm[q] = ffma2(ci, Ex2, accIm[q]);
            accIm[q] = ffma2(cr, Eyn2, accIm[q]);
        }
        float nx = E.x * S.x - E.y * S.y;
        float ny = E.x * S.y + E.y * S.x;
        E = make_float2(nx, ny);
    }
    __syncthreads();

    float* red2 = Xs;   // 256*37 = 9472 <= 16640
    {
        float* my = red2 + t * 37;
#pragma unroll
        for (int q = 0; q < 9; q++) {
            float2 a = upk(accRe[q]);
            my[2 * q] = a.x; my[2 * q + 1] = a.y;
            float2 b = upk(accIm[q]);
            my[18 + 2 * q] = b.x; my[19 + 2 * q] = b.y;
        }
    }
    __syncthreads();

    const float sc = 1.f / 256.f;
    for (int pp = t; pp < F; pp += 256) {
        int kxo = pp / 17, ky = pp % 17;
        float re = 0.f, im = 0.f;
#pragma unroll
        for (int c = 0; c < 8; c++) {
            const float* s = red2 + (c * 32 + kxo) * 37;
            re += s[ky];
            im += s[18 + ky];
        }
        g_XfT[(size_t)pp * IMG + img] = make_float2(re * sc, im * sc);
    }
}

// ---------------------------------------------------------------------------
// K3: per-frequency complex channel mix, fully coalesced, 256 threads.
// ---------------------------------------------------------------------------
__global__ void __launch_bounds__(256) k3_mix() {
    __shared__ __align__(16) float2 Xs[512];
    __shared__ __align__(16) float2 Ws[4096];
    int f = blockIdx.x;

    const float4* wsrc = reinterpret_cast<const float4*>(g_WT + (size_t)f * 4096);
    float4* wd = reinterpret_cast<float4*>(Ws);
    for (int t = threadIdx.x; t < 2048; t += 256) wd[t] = wsrc[t];
    const float4* xsrc = reinterpret_cast<const float4*>(g_XfT + (size_t)f * IMG);
    float4* xd = reinterpret_cast<float4*>(Xs);
    if (threadIdx.x < 256) xd[threadIdx.x] = xsrc[threadIdx.x];
    __syncthreads();

#pragma unroll
    for (int u = 0; u < 2; u++) {
        int t2 = threadIdx.x + u * 256;
        int b = t2 >> 6, co = t2 & 63;
        float yr = 0.f, yi = 0.f;
#pragma unroll 8
        for (int i = 0; i < 64; i++) {
            float2 X = Xs[b * 64 + i];
            float2 W = Ws[i * 64 + co];
            yr += X.x * W.x - X.y * W.y;
            yi += X.x * W.y + X.y * W.x;
        }
        g_YfT[(size_t)f * IMG + t2] = make_float2(yr, yi);
    }
}

// ---------------------------------------------------------------------------
// K45: fused inverse h-DFT + folded w-synthesis. Block per image.
// Phase A: thread per h; twiddle recurrence E(kx+1) = E(kx)*g_Estep[h];
// writes Gp[col][h] (conflict-free column stores).
// Phase B: thread (w = t&127, half); TWO row-pairs per iteration via
// broadcast LDS.128 of Gp (pp even -> 16B aligned); ce/cs in regs;
// E +- O fold; w==0 lanes emit column 128.
// ---------------------------------------------------------------------------
__global__ void __launch_bounds__(256) k45_fused(const float* __restrict__ bias,
                                                float* __restrict__ out) {
    extern __shared__ __align__(16) float sm4[];
    float* Ysr = sm4;                    // 32*24
    float* Ysi = Ysr + 32 * 24;          // 32*24
    float* Gp  = Ysi + 32 * 24;          // 36*256 (base at byte 6144)

    int img = blockIdx.x;
    for (int i = threadIdx.x; i < 32 * 24; i += 256) { Ysr[i] = 0.f; Ysi[i] = 0.f; }
    __syncthreads();
    for (int i = threadIdx.x; i < F; i += 256) {
        float2 y = g_YfT[(size_t)i * IMG + img];
        int kx = i / 17, ky = i % 17;
        Ysr[kx * 24 + ky] = y.x;
        Ysi[kx * 24 + ky] = y.y;
    }
    __syncthreads();

    // ---- Phase A: inverse h-DFT -> Gp[col][h] (twiddle recurrence) ----
    {
        int h = threadIdx.x;
        float2 S = __ldg(&g_Estep[h]);
        float2 E = make_float2(1.f, 0.f);
        u64 grp[9], gip[9];
#pragma unroll
        for (int q = 0; q < 9; q++) { grp[q] = 0; gip[q] = 0; }

#pragma unroll 4
        for (int kx = 0; kx < 32; kx++) {
            u64 Ex2  = pk(E.x, E.x);
            u64 Ey2  = pk(E.y, E.y);
            u64 Eyn2 = pk(-E.y, -E.y);
            const u64* yr = reinterpret_cast<const u64*>(Ysr + kx * 24);
            const u64* yi = reinterpret_cast<const u64*>(Ysi + kx * 24);
#pragma unroll
            for (int q = 0; q < 9; q++) {
                u64 Yr = yr[q], Yi = yi[q];
                grp[q] = ffma2(Yr, Ex2, grp[q]);
                grp[q] = ffma2(Yi, Eyn2, grp[q]);
                gip[q] = ffma2(Yr, Ey2, gip[q]);
                gip[q] = ffma2(Yi, Ex2, gip[q]);
            }
            float nx = E.x * S.x - E.y * S.y;
            float ny = E.x * S.y + E.y * S.x;
            E = make_float2(nx, ny);
        }
#pragma unroll
        for (int q = 0; q < 9; q++) {
            float2 a = upk(grp[q]);
            Gp[(2 * q) * 256 + h]     = a.x;
            Gp[(2 * q + 1) * 256 + h] = a.y;
            float2 b = upk(gip[q]);
            Gp[(18 + 2 * q) * 256 + h] = b.x;
            Gp[(19 + 2 * q) * 256 + h] = b.y;
        }
    }
    __syncthreads();

    // ---- Phase B: folded w-synthesis, two row-pairs per iteration ----
    int w = threadIdx.x & 127, half = threadIdx.x >> 7;
    u64 ce2[17], cs2[17];
    const u64* PC = reinterpret_cast<const u64*>(g_PC5);
    const u64* PS = reinterpret_cast<const u64*>(g_PS5);
#pragma unroll
    for (int k = 0; k < 17; k++) {
        ce2[k] = PC[k * 128 + w];
        cs2[k] = PS[k * 128 + w];
    }
    float bv = bias[img & 63];
    u64 m0 = pk(1.f / 256.f, 1.f / 256.f);
    u64 mp = pk(2.f / 256.f, 2.f / 256.f);
    u64 mn = pk(-2.f / 256.f, -2.f / 256.f);
    float* ob = out + (size_t)img * 65536;

#pragma unroll 2
    for (int qq = 0; qq < 32; qq++) {
        int pp = half * 64 + 2 * qq;         // even -> 16B-aligned gp
        const ulonglong2* gp =
            reinterpret_cast<const ulonglong2*>(Gp + 2 * pp);  // +k*64 per col
        u64 Ea0 = 0, Ea1 = 0, Oa0 = 0, Oa1 = 0;
#pragma unroll
        for (int k = 0; k < 17; k++) {
            ulonglong2 g = gp[k * 64];
            Ea0 = ffma2(g.x, ce2[k], Ea0);
            Ea1 = ffma2(g.y, ce2[k], Ea1);
        }
#pragma unroll
        for (int k = 1; k < 17; k++) {
            ulonglong2 g = gp[(18 + k) * 64];
            Oa0 = ffma2(g.x, cs2[k], Oa0);
            Oa1 = ffma2(g.y, cs2[k], Oa1);
        }
        float2 e0 = upk(Ea0), e1 = upk(Ea1), o0 = upk(Oa0), o1 = upk(Oa1);
        float* r0 = ob + (size_t)(2 * pp) * 256;
        r0[w]       = e0.x + o0.x + bv;
        r0[256 + w] = e0.y + o0.y + bv;
        r0[512 + w] = e1.x + o1.x + bv;
        r0[768 + w] = e1.y + o1.y + bv;
        if (w) {
            int wm = 256 - w;
            r0[wm]       = e0.x - o0.x + bv;
            r0[256 + wm] = e0.y - o0.y + bv;
            r0[512 + wm] = e1.x - o1.x + bv;
            r0[768 + wm] = e1.y - o1.y + bv;
        } else {
            // Column 128: cos = (-1)^ky, sin = 0
            u64 E80 = 0, E81 = 0;
#pragma unroll
            for (int k = 0; k < 17; k++) {
                ulonglong2 g = gp[k * 64];
                u64 mm = (k == 0) ? m0 : ((k & 1) ? mn : mp);
                E80 = ffma2(g.x, mm, E80);
                E81 = ffma2(g.y, mm, E81);
            }
            float2 a8 = upk(E80), b8 = upk(E81);
            r0[128]       = a8.x + bv;
            r0[256 + 128] = a8.y + bv;
            r0[512 + 128] = b8.x + bv;
            r0[768 + 128] = b8.y + bv;
        }
    }
}

// ---------------------------------------------------------------------------
extern "C" void kernel_launch(void* const* d_in, const int* in_sizes, int n_in,
                              void* d_out, int out_size) {
    const float* x    = (const float*)d_in[0];
    const float* wr   = (const float*)d_in[1];
    const float* wi   = (const float*)d_in[2];
    const float* bias = (const float*)d_in[3];
    float* out = (float*)d_out;

    const int K2B_SMEM = 2 * 16 * 545 * 4;            // 69760 B
    const int K12_SMEM = (16640 + 9216) * 4;          // 103424 B
    const int K45_SMEM = (2 * 32 * 24 + 36 * 256) * 4; // 43008 B
    cudaFuncSetAttribute(k2b_wt, cudaFuncAttributeMaxDynamicSharedMemorySize, K2B_SMEM);
    cudaFuncSetAttribute(k12_fwd, cudaFuncAttributeMaxDynamicSharedMemorySize, K12_SMEM);
    cudaFuncSetAttribute(k45_fused, cudaFuncAttributeMaxDynamicSharedMemorySize, K45_SMEM);

    k0a_tables<<<64, 256>>>();
    k0b_tables<<<16, 256>>>();
    k2b_wt<<<256, 256, K2B_SMEM>>>(wr, wi);
    k12_fwd<<<IMG, 256, K12_SMEM>>>(x);      // captured launch (index 3)
    k3_mix<<<F, 256>>>();
    k45_fused<<<IMG, 256, K45_SMEM>>>(bias, out);
}

// round 11
// speedup vs baseline: 1.1012x; 1.1012x over previous
#include <cuda_runtime.h>
#include <math.h>

// MHFSpectralConv2D via pruned-DFT factorization, round 11.
// k12 phase 1 rebuilt: 2 rows/thread (each table LDS feeds both rows),
// 16 k-parts, conflict-free strides (Xs 272, TK 38), 2-round bfly + smem
// quartet reduction. Phase 2 + k45 keep the validated twiddle recurrence.

namespace {
constexpr int IMG = 512;                      // B*C = 8*64
constexpr int MX = 32, MY = 17, F = MX * MY;  // 544 live freqs
constexpr int XSS = 272;                      // k12 x-stage row stride (=16 mod 32)
}

// ---- persistent device scratch / tables ----
__device__ float  g_TK1[129 * 38];   // [w][38]: cos ky0..16 |0| -sin ky0..16 |0,0,0
__device__ float2 g_E1[32];          // e(+2pi kx/256)
__device__ float2 g_Eseed[256];      // [ch*32+kx] = e(+2pi kx*32*ch/256)
__device__ float2 g_Estep[256];      // [h] = e(+2pi h/256)
__device__ float2 g_PC5[17 * 128];   // K5 cos coef, duplicated lanes
__device__ float2 g_PS5[17 * 128];   // K5 sin coef, duplicated lanes
__device__ float2 g_XfT[(size_t)F * IMG];     // [f][img]
__device__ float2 g_WT[(size_t)F * 4096];     // [f][i*64+co]
__device__ float2 g_YfT[(size_t)F * IMG];     // [f][img]

// ---- f32x2 helpers ----
typedef unsigned long long u64;
__device__ __forceinline__ u64 ffma2(u64 a, u64 b, u64 c) {
    u64 d;
    asm("fma.rn.f32x2 %0, %1, %2, %3;" : "=l"(d) : "l"(a), "l"(b), "l"(c));
    return d;
}
__device__ __forceinline__ float2 upk(u64 v) {
    float2 r;
    asm("mov.b64 {%0,%1}, %2;" : "=f"(r.x), "=f"(r.y) : "l"(v));
    return r;
}
__device__ __forceinline__ u64 pk(float a, float b) {
    u64 v;
    asm("mov.b64 %0, {%1,%2};" : "=l"(v) : "f"(a), "f"(b));
    return v;
}

// ---------------------------------------------------------------------------
// K0a/K0b: trig tables (exact integer mod-256 reduction).
// ---------------------------------------------------------------------------
__global__ void k0a_tables() {
    int tid = blockIdx.x * blockDim.x + threadIdx.x;
    int nt  = blockDim.x * gridDim.x;
    for (int idx = tid; idx < 129 * 38; idx += nt) {
        int w = idx / 38, c = idx % 38;
        float v = 0.f;
        if (c < 17) {
            int m = (c * w) & 255; float s, co;
            sincospif((float)m * (1.f / 128.f), &s, &co);
            v = co;
        } else if (c >= 18 && c < 35) {
            int ky = c - 18;
            int m = (ky * w) & 255; float s, co;
            sincospif((float)m * (1.f / 128.f), &s, &co);
            v = -s;
        }
        g_TK1[idx] = v;
    }
    for (int idx = tid; idx < 256; idx += nt) {
        float s, co;
        if (idx < 32) {
            int m = idx & 255;
            sincospif((float)m * (1.f / 128.f), &s, &co);
            g_E1[idx] = make_float2(co, s);
        }
        {
            int ch = idx >> 5, kx = idx & 31;
            int m = (32 * ch * kx) & 255;
            sincospif((float)m * (1.f / 128.f), &s, &co);
            g_Eseed[idx] = make_float2(co, s);
        }
        {
            int m = idx & 255;
            sincospif((float)m * (1.f / 128.f), &s, &co);
            g_Estep[idx] = make_float2(co, s);
        }
    }
}
__global__ void k0b_tables() {
    int tid = blockIdx.x * blockDim.x + threadIdx.x;
    int nt  = blockDim.x * gridDim.x;
    for (int idx = tid; idx < 17 * 128; idx += nt) {
        int k = idx >> 7, w = idx & 127;
        int m = (k * w) & 255; float s, co;
        sincospif((float)m * (1.f / 128.f), &s, &co);
        float ce = (k == 0) ? (1.f / 256.f) : co * (2.f / 256.f);
        float cs = -s * (2.f / 256.f);
        g_PC5[idx] = make_float2(ce, ce);
        g_PS5[idx] = make_float2(cs, cs);
    }
}

// ---------------------------------------------------------------------------
// K2b: weight transpose -> WT[f][i*64 + co] (co = hd*16 + o).
// ---------------------------------------------------------------------------
__global__ void __launch_bounds__(256) k2b_wt(const float* __restrict__ wr,
                                             const float* __restrict__ wi) {
    extern __shared__ float smw[];
    float* smr = smw;            // 16*545
    float* smi = smw + 16 * 545; // 16*545

    int hd = blockIdx.x >> 6, i = blockIdx.x & 63;
    size_t base = (size_t)((hd * 64 + i) * 16) * F;   // 16 rows x 544

    const float4* wr4 = reinterpret_cast<const float4*>(wr + base);
    const float4* wi4 = reinterpret_cast<const float4*>(wi + base);
    for (int idx = threadIdx.x; idx < 2176; idx += 256) {
        int o = (idx * 4) / 544, fb = (idx * 4) % 544;
        float4 a = wr4[idx];
        float4 b = wi4[idx];
        float* dr = smr + o * 545 + fb;
        float* di = smi + o * 545 + fb;
        dr[0] = a.x; dr[1] = a.y; dr[2] = a.z; dr[3] = a.w;
        di[0] = b.x; di[1] = b.y; di[2] = b.z; di[3] = b.w;
    }
    __syncthreads();

    int cobase = i * 64 + hd * 16;
    for (int idx = threadIdx.x; idx < 8704; idx += 256) {
        int f = idx >> 4, o = idx & 15;
        g_WT[(size_t)f * 4096 + cobase + o] =
            make_float2(smr[o * 545 + f], smi[o * 545 + f]);
    }
}

// ---------------------------------------------------------------------------
// K12: fused forward transform, block per image (512 blocks, 256 threads).
// Phase 1 (x8 chunks of 32 rows): folded w-DFT, 2 rows/thread, 16 k-parts.
// Thread (rr = t>>4, p = t&15) handles rows rr, rr+16 and w = 16j+p+1,
// j=0..7. Xs stride 272 (=16 mod 32): the two rr-groups' bank sets are
// disjoint -> conflict-free fold reads. TK stride 38: banks 6p+6 distinct
// over p -> conflict-free broadcast table reads feeding BOTH rows.
// Reduce 16 partials: 2 bfly rounds -> quartet lanes (p&3==0) write red
// (stride 37, aliases Xs, barrier-separated) -> Aw[row][36] sums 4 parts.
// Phase 2: h-DFT from smem Aw (broadcast u64) + twiddle recurrence.
// ---------------------------------------------------------------------------
__global__ void __launch_bounds__(256, 2) k12_fwd(const float* __restrict__ x) {
    extern __shared__ __align__(16) float sm[];
    float* TK = sm;              // 4902 (padded to 4904)
    float* Xs = sm + 4904;       // 32*272 = 8704 (red aliases here)
    float* Aw = sm + 13608;      // 256*36 = 9216
    // red2 (phase 2) aliases [0, 9472) over dead TK+Xs.

    int t = threadIdx.x;
    int img = blockIdx.x;
    int p = t & 15, rr = t >> 4;         // rr 0..15
    bool wrt = ((p & 3) == 0);
    float* red = Xs;                     // 32 rows * 4 parts * 37 = 4736

    for (int i = t; i < 129 * 38; i += 256) TK[i] = g_TK1[i];

    for (int chunk = 0; chunk < 8; chunk++) {
        __syncthreads();   // prior red consumers done; Xs free; TK ready
        const float4* xg = reinterpret_cast<const float4*>(
            x + (size_t)img * 65536 + chunk * 8192);
#pragma unroll
        for (int k = 0; k < 8; k++) {
            int fidx = k * 256 + t;
            int row = fidx >> 6, c4 = fidx & 63;
            float4 v = __ldcs(xg + fidx);
            *reinterpret_cast<float4*>(Xs + row * XSS + c4 * 4) = v;
        }
        __syncthreads();

        const float* xr0 = Xs + rr * XSS;
        const float* xr1 = Xs + (rr + 16) * XSS;

        u64 a0[18], a1[18];
#pragma unroll
        for (int q = 0; q < 18; q++) { a0[q] = 0; a1[q] = 0; }

#pragma unroll 2
        for (int j = 0; j < 8; j++) {
            int w = 16 * j + p + 1;
            float f0 = xr0[w], m0 = xr0[256 - w];
            float f1 = xr1[w], m1 = xr1[256 - w];
            u64 uu0 = pk(f0 + m0, f0 + m0), vv0 = pk(f0 - m0, f0 - m0);
            u64 uu1 = pk(f1 + m1, f1 + m1), vv1 = pk(f1 - m1, f1 - m1);
            const u64* tu = reinterpret_cast<const u64*>(TK + w * 38);
#pragma unroll
            for (int q = 0; q < 9; q++) {
                u64 tv = tu[q];
                a0[q] = ffma2(tv, uu0, a0[q]);
                a1[q] = ffma2(tv, uu1, a1[q]);
            }
#pragma unroll
            for (int q = 9; q < 18; q++) {
                u64 tv = tu[q];
                a0[q] = ffma2(tv, vv0, a0[q]);
                a1[q] = ffma2(tv, vv1, a1[q]);
            }
        }
        if (p == 0) {
            float x00 = xr0[0], x80 = xr0[128];
            float ea0 = x00 - x80, eb0 = x00 + x80;
            u64 e0 = pk(ea0, eb0), one2 = pk(1.f, 1.f);
            float x01 = xr1[0], x81 = xr1[128];
            float ea1 = x01 - x81, eb1 = x01 + x81;
            u64 e1 = pk(ea1, eb1);
#pragma unroll
            for (int q = 0; q < 8; q++) {
                a0[q] = ffma2(one2, e0, a0[q]);
                a1[q] = ffma2(one2, e1, a1[q]);
            }
            a0[8] = ffma2(one2, pk(ea0, 0.f), a0[8]);
            a1[8] = ffma2(one2, pk(ea1, 0.f), a1[8]);
        }

        // All warps done reading Xs before red (aliased) is written.
        __syncthreads();

        int rb0 = (rr * 4 + (p >> 2)) * 37;
        int rb1 = ((rr + 16) * 4 + (p >> 2)) * 37;
#pragma unroll
        for (int q = 0; q < 18; q++) {
            float2 v = upk(a0[q]);
            v.x += __shfl_xor_sync(0xffffffffu, v.x, 1);
            v.y += __shfl_xor_sync(0xffffffffu, v.y, 1);
            v.x += __shfl_xor_sync(0xffffffffu, v.x, 2);
            v.y += __shfl_xor_sync(0xffffffffu, v.y, 2);
            if (wrt) { red[rb0 + 2 * q] = v.x; red[rb0 + 2 * q + 1] = v.y; }
            float2 u = upk(a1[q]);
            u.x += __shfl_xor_sync(0xffffffffu, u.x, 1);
            u.y += __shfl_xor_sync(0xffffffffu, u.y, 1);
            u.x += __shfl_xor_sync(0xffffffffu, u.x, 2);
            u.y += __shfl_xor_sync(0xffffffffu, u.y, 2);
            if (wrt) { red[rb1 + 2 * q] = u.x; red[rb1 + 2 * q + 1] = u.y; }
        }
        __syncthreads();

        for (int idx = t; idx < 32 * 36; idx += 256) {
            int row = idx / 36, c = idx % 36;
            const float* s = red + (row * 4) * 37 + c;
            Aw[(chunk * 32 + row) * 36 + c] = (s[0] + s[37]) + (s[74] + s[111]);
        }
    }
    __syncthreads();

    // ---- Phase 2: h-DFT with twiddle recurrence ----
    int kx = t & 31, ch = t >> 5;
    float2 E = g_Eseed[ch * 32 + kx];
    float2 S = g_E1[kx];
    u64 accRe[9], accIm[9];
#pragma unroll
    for (int q = 0; q < 9; q++) { accRe[q] = 0; accIm[q] = 0; }

#pragma unroll 4
    for (int hh = 0; hh < 32; hh++) {
        int h = ch * 32 + hh;
        u64 Ex2  = pk(E.x, E.x);
        u64 Ey2  = pk(E.y, E.y);
        u64 Eyn2 = pk(-E.y, -E.y);
        const u64* c2 = reinterpret_cast<const u64*>(Aw + h * 36);
#pragma unroll
        for (int q = 0; q < 9; q++) {
            u64 cr = c2[q], ci = c2[9 + q];
            accRe[q] = ffma2(cr, Ex2, accRe[q]);
            accRe[q] = ffma2(ci, Ey2, accRe[q]);
            accIm[q] = ffma2(ci, Ex2, accIm[q]);
            accIm[q] = ffma2(cr, Eyn2, accIm[q]);
        }
        float nx = E.x * S.x - E.y * S.y;
        float ny = E.x * S.y + E.y * S.x;
        E = make_float2(nx, ny);
    }
    __syncthreads();

    float* red2 = sm;   // 256*37 = 9472 <= 13608 (TK+Xs dead)
    {
        float* my = red2 + t * 37;
#pragma unroll
        for (int q = 0; q < 9; q++) {
            float2 a = upk(accRe[q]);
            my[2 * q] = a.x; my[2 * q + 1] = a.y;
            float2 b = upk(accIm[q]);
            my[18 + 2 * q] = b.x; my[19 + 2 * q] = b.y;
        }
    }
    __syncthreads();

    const float sc = 1.f / 256.f;
    for (int pp = t; pp < F; pp += 256) {
        int kxo = pp / 17, ky = pp % 17;
        float re = 0.f, im = 0.f;
#pragma unroll
        for (int c = 0; c < 8; c++) {
            const float* s = red2 + (c * 32 + kxo) * 37;
            re += s[ky];
            im += s[18 + ky];
        }
        g_XfT[(size_t)pp * IMG + img] = make_float2(re * sc, im * sc);
    }
}

// ---------------------------------------------------------------------------
// K3: per-frequency complex channel mix, fully coalesced, 256 threads.
// ---------------------------------------------------------------------------
__global__ void __launch_bounds__(256) k3_mix() {
    __shared__ __align__(16) float2 Xs[512];
    __shared__ __align__(16) float2 Ws[4096];
    int f = blockIdx.x;

    const float4* wsrc = reinterpret_cast<const float4*>(g_WT + (size_t)f * 4096);
    float4* wd = reinterpret_cast<float4*>(Ws);
    for (int t = threadIdx.x; t < 2048; t += 256) wd[t] = wsrc[t];
    const float4* xsrc = reinterpret_cast<const float4*>(g_XfT + (size_t)f * IMG);
    float4* xd = reinterpret_cast<float4*>(Xs);
    if (threadIdx.x < 256) xd[threadIdx.x] = xsrc[threadIdx.x];
    __syncthreads();

#pragma unroll
    for (int u = 0; u < 2; u++) {
        int t2 = threadIdx.x + u * 256;
        int b = t2 >> 6, co = t2 & 63;
        float yr = 0.f, yi = 0.f;
#pragma unroll 8
        for (int i = 0; i < 64; i++) {
            float2 X = Xs[b * 64 + i];
            float2 W = Ws[i * 64 + co];
            yr += X.x * W.x - X.y * W.y;
            yi += X.x * W.y + X.y * W.x;
        }
        g_YfT[(size_t)f * IMG + t2] = make_float2(yr, yi);
    }
}

// ---------------------------------------------------------------------------
// K45: fused inverse h-DFT + folded w-synthesis. Block per image.
// (Validated in R10: recurrence phase A, LDS.128 row-quad phase B.)
// ---------------------------------------------------------------------------
__global__ void __launch_bounds__(256) k45_fused(const float* __restrict__ bias,
                                                float* __restrict__ out) {
    extern __shared__ __align__(16) float sm4[];
    float* Ysr = sm4;                    // 32*24
    float* Ysi = Ysr + 32 * 24;          // 32*24
    float* Gp  = Ysi + 32 * 24;          // 36*256 (base at byte 6144)

    int img = blockIdx.x;
    for (int i = threadIdx.x; i < 32 * 24; i += 256) { Ysr[i] = 0.f; Ysi[i] = 0.f; }
    __syncthreads();
    for (int i = threadIdx.x; i < F; i += 256) {
        float2 y = g_YfT[(size_t)i * IMG + img];
        int kx = i / 17, ky = i % 17;
        Ysr[kx * 24 + ky] = y.x;
        Ysi[kx * 24 + ky] = y.y;
    }
    __syncthreads();

    // ---- Phase A: inverse h-DFT -> Gp[col][h] (twiddle recurrence) ----
    {
        int h = threadIdx.x;
        float2 S = __ldg(&g_Estep[h]);
        float2 E = make_float2(1.f, 0.f);
        u64 grp[9], gip[9];
#pragma unroll
        for (int q = 0; q < 9; q++) { grp[q] = 0; gip[q] = 0; }

#pragma unroll 4
        for (int kx = 0; kx < 32; kx++) {
            u64 Ex2  = pk(E.x, E.x);
            u64 Ey2  = pk(E.y, E.y);
            u64 Eyn2 = pk(-E.y, -E.y);
            const u64* yr = reinterpret_cast<const u64*>(Ysr + kx * 24);
            const u64* yi = reinterpret_cast<const u64*>(Ysi + kx * 24);
#pragma unroll
            for (int q = 0; q < 9; q++) {
                u64 Yr = yr[q], Yi = yi[q];
                grp[q] = ffma2(Yr, Ex2, grp[q]);
                grp[q] = ffma2(Yi, Eyn2, grp[q]);
                gip[q] = ffma2(Yr, Ey2, gip[q]);
                gip[q] = ffma2(Yi, Ex2, gip[q]);
            }
            float nx = E.x * S.x - E.y * S.y;
            float ny = E.x * S.y + E.y * S.x;
            E = make_float2(nx, ny);
        }
#pragma unroll
        for (int q = 0; q < 9; q++) {
            float2 a = upk(grp[q]);
            Gp[(2 * q) * 256 + h]     = a.x;
            Gp[(2 * q + 1) * 256 + h] = a.y;
            float2 b = upk(gip[q]);
            Gp[(18 + 2 * q) * 256 + h] = b.x;
            Gp[(19 + 2 * q) * 256 + h] = b.y;
        }
    }
    __syncthreads();

    // ---- Phase B: folded w-synthesis, two row-pairs per iteration ----
    int w = threadIdx.x & 127, half = threadIdx.x >> 7;
    u64 ce2[17], cs2[17];
    const u64* PC = reinterpret_cast<const u64*>(g_PC5);
    const u64* PS = reinterpret_cast<const u64*>(g_PS5);
#pragma unroll
    for (int k = 0; k < 17; k++) {
        ce2[k] = PC[k * 128 + w];
        cs2[k] = PS[k * 128 + w];
    }
    float bv = bias[img & 63];
    u64 m0 = pk(1.f / 256.f, 1.f / 256.f);
    u64 mp = pk(2.f / 256.f, 2.f / 256.f);
    u64 mn = pk(-2.f / 256.f, -2.f / 256.f);
    float* ob = out + (size_t)img * 65536;

#pragma unroll 2
    for (int qq = 0; qq < 32; qq++) {
        int pp = half * 64 + 2 * qq;         // even -> 16B-aligned gp
        const ulonglong2* gp =
            reinterpret_cast<const ulonglong2*>(Gp + 2 * pp);  // +k*64 per col
        u64 Ea0 = 0, Ea1 = 0, Oa0 = 0, Oa1 = 0;
#pragma unroll
        for (int k = 0; k < 17; k++) {
            ulonglong2 g = gp[k * 64];
            Ea0 = ffma2(g.x, ce2[k], Ea0);
            Ea1 = ffma2(g.y, ce2[k], Ea1);
        }
#pragma unroll
        for (int k = 1; k < 17; k++) {
            ulonglong2 g = gp[(18 + k) * 64];
            Oa0 = ffma2(g.x, cs2[k], Oa0);
            Oa1 = ffma2(g.y, cs2[k], Oa1);
        }
        float2 e0 = upk(Ea0), e1 = upk(Ea1), o0 = upk(Oa0), o1 = upk(Oa1);
        float* r0 = ob + (size_t)(2 * pp) * 256;
        r0[w]       = e0.x + o0.x + bv;
        r0[256 + w] = e0.y + o0.y + bv;
        r0[512 + w] = e1.x + o1.x + bv;
        r0[768 + w] = e1.y + o1.y + bv;
        if (w) {
            int wm = 256 - w;
            r0[wm]       = e0.x - o0.x + bv;
            r0[256 + wm] = e0.y - o0.y + bv;
            r0[512 + wm] = e1.x - o1.x + bv;
            r0[768 + wm] = e1.y - o1.y + bv;
        } else {
            // Column 128: cos = (-1)^ky, sin = 0
            u64 E80 = 0, E81 = 0;
#pragma unroll
            for (int k = 0; k < 17; k++) {
                ulonglong2 g = gp[k * 64];
                u64 mm = (k == 0) ? m0 : ((k & 1) ? mn : mp);
                E80 = ffma2(g.x, mm, E80);
                E81 = ffma2(g.y, mm, E81);
            }
            float2 a8 = upk(E80), b8 = upk(E81);
            r0[128]       = a8.x + bv;
            r0[256 + 128] = a8.y + bv;
            r0[512 + 128] = b8.x + bv;
            r0[768 + 128] = b8.y + bv;
        }
    }
}

// ---------------------------------------------------------------------------
extern "C" void kernel_launch(void* const* d_in, const int* in_sizes, int n_in,
                              void* d_out, int out_size) {
    const float* x    = (const float*)d_in[0];
    const float* wr   = (const float*)d_in[1];
    const float* wi   = (const float*)d_in[2];
    const float* bias = (const float*)d_in[3];
    float* out = (float*)d_out;

    const int K2B_SMEM = 2 * 16 * 545 * 4;             // 69760 B
    const int K12_SMEM = (4904 + 8704 + 9216) * 4;     // 91296 B
    const int K45_SMEM = (2 * 32 * 24 + 36 * 256) * 4; // 43008 B
    cudaFuncSetAttribute(k2b_wt, cudaFuncAttributeMaxDynamicSharedMemorySize, K2B_SMEM);
    cudaFuncSetAttribute(k12_fwd, cudaFuncAttributeMaxDynamicSharedMemorySize, K12_SMEM);
    cudaFuncSetAttribute(k45_fused, cudaFuncAttributeMaxDynamicSharedMemorySize, K45_SMEM);

    k0a_tables<<<64, 256>>>();
    k0b_tables<<<16, 256>>>();
    k2b_wt<<<256, 256, K2B_SMEM>>>(wr, wi);
    k12_fwd<<<IMG, 256, K12_SMEM>>>(x);      // captured launch (index 3)
    k3_mix<<<F, 256>>>();
    k45_fused<<<IMG, 256, K45_SMEM>>>(bias, out);
}